// round 1
// baseline (speedup 1.0000x reference)
#include <cuda_runtime.h>
#include <math.h>

// Problem constants
#define MTOT 131072      // B*A tokens
#define TPB  128         // tokens per block == threads per block
#define NBLK (MTOT / TPB)

// Shared-memory layout (float offsets). Rows padded so float4 accesses are
// conflict-free (row stride in bytes == 16 mod 128).
#define OFF_SXH   0        // [128][68]  x_in half tile / scratch row (h1, hnew park)
#define OFF_SHH   8704     // [128][68]  h_in tile, later h
#define OFF_SHX   17408    // [128][68]  x (post-fc)
#define OFF_SWT   26112    // 24576 floats: phase-staged weights
#define OFF_SGATE 50688    // [128][9]   gate weights per token
#define OFF_SEO   51840    // [128][36]  output staging
#define SMEM_FLOATS 56448  // 225,792 bytes

#define DOT4(accv, a, b) \
    accv = fmaf((a).x, (b).x, accv); \
    accv = fmaf((a).y, (b).y, accv); \
    accv = fmaf((a).z, (b).z, accv); \
    accv = fmaf((a).w, (b).w, accv);

__device__ __forceinline__ float sig_(float v) { return 1.0f / (1.0f + __expf(-v)); }

__global__ void __launch_bounds__(TPB, 1) msp_kernel(
    const float* __restrict__ xin,   const float* __restrict__ hin,
    const float* __restrict__ fc_w,  const float* __restrict__ fc_b,
    const float* __restrict__ w_ih,  const float* __restrict__ w_hh,
    const float* __restrict__ b_ih,  const float* __restrict__ b_hh,
    const float* __restrict__ e_w1,  const float* __restrict__ e_b1,
    const float* __restrict__ e_w2,  const float* __restrict__ e_b2,
    const float* __restrict__ gate_w,const float* __restrict__ gate_b,
    float* __restrict__ out)
{
    extern __shared__ float sm[];
    float* sxh   = sm + OFF_SXH;
    float* shh   = sm + OFF_SHH;
    float* shx   = sm + OFF_SHX;
    float* swt   = sm + OFF_SWT;
    float* sgate = sm + OFF_SGATE;
    float* seo   = sm + OFF_SEO;

    const int t    = threadIdx.x;
    const int base = blockIdx.x * TPB;

    // ---------------- P0: stage h_in tile, x_in half 0, fc_w + gate_w ----------------
    {
        const float4* hsrc = (const float4*)hin;
        float4* hdst = (float4*)shh;
        #pragma unroll
        for (int i = t; i < TPB * 16; i += TPB) {
            int r = i >> 4, c = i & 15;
            hdst[r * 17 + c] = hsrc[(size_t)(base + r) * 16 + c];
        }
        const float4* xsrc = (const float4*)xin;
        float4* xdst = (float4*)sxh;
        #pragma unroll
        for (int i = t; i < TPB * 16; i += TPB) {
            int r = i >> 4, c = i & 15;
            xdst[r * 17 + c] = xsrc[(size_t)(base + r) * 32 + c];  // columns 0..63
        }
        const float4* s1 = (const float4*)fc_w;   float4* d1 = (float4*)swt;
        #pragma unroll
        for (int i = t; i < 2048; i += TPB) d1[i] = s1[i];          // fc_w  [64][128]
        const float4* s2 = (const float4*)gate_w; float4* d2 = (float4*)(swt + 8192);
        #pragma unroll
        for (int i = t; i < 256; i += TPB) d2[i] = s2[i];           // gate_w [8][128]
    }
    __syncthreads();

    // ---------------- P1: x = relu(x_in @ fc_w^T + fc_b), gate pre-activation ----------
    float acc[64];
    float gacc[8];
    #pragma unroll
    for (int j = 0; j < 64; ++j) acc[j] = __ldg(fc_b + j);
    #pragma unroll
    for (int n = 0; n < 8; ++n)  gacc[n] = __ldg(gate_b + n);

    #pragma unroll 1
    for (int half = 0; half < 2; ++half) {
        if (half == 1) {
            __syncthreads();
            const float4* xsrc = (const float4*)xin;
            float4* xdst = (float4*)sxh;
            #pragma unroll
            for (int i = t; i < TPB * 16; i += TPB) {
                int r = i >> 4, c = i & 15;
                xdst[r * 17 + c] = xsrc[(size_t)(base + r) * 32 + 16 + c];  // columns 64..127
            }
            __syncthreads();
        }
        const int kg0 = half * 64;
        #pragma unroll 1
        for (int k = 0; k < 64; k += 4) {
            float4 xv = *(const float4*)(sxh + t * 68 + k);
            const int kg = kg0 + k;
            #pragma unroll
            for (int j = 0; j < 64; ++j) {
                float4 wv = *(const float4*)(swt + j * 128 + kg);
                DOT4(acc[j], xv, wv);
            }
            #pragma unroll
            for (int n = 0; n < 8; ++n) {
                float4 wv = *(const float4*)(swt + 8192 + n * 128 + kg);
                DOT4(gacc[n], xv, wv);
            }
        }
    }
    #pragma unroll
    for (int c = 0; c < 16; ++c) {
        float4 v;
        v.x = fmaxf(acc[c * 4 + 0], 0.f); v.y = fmaxf(acc[c * 4 + 1], 0.f);
        v.z = fmaxf(acc[c * 4 + 2], 0.f); v.w = fmaxf(acc[c * 4 + 3], 0.f);
        *(float4*)(shx + t * 68 + c * 4) = v;
    }
    #pragma unroll
    for (int n = 0; n < 8; ++n) sgate[t * 9 + n] = sig_(gacc[n]);

    __syncthreads();
    // stage GRU weights: w_ih [192][64] -> swt[0..12288), w_hh -> swt[12288..24576)
    {
        const float4* s1 = (const float4*)w_ih; float4* d1 = (float4*)swt;
        #pragma unroll
        for (int i = t; i < 3072; i += TPB) d1[i] = s1[i];
        const float4* s2 = (const float4*)w_hh; float4* d2 = (float4*)(swt + 12288);
        #pragma unroll
        for (int i = t; i < 3072; i += TPB) d2[i] = s2[i];
    }
    __syncthreads();

    // ---------------- P2: GRU cell ----------------
    #pragma unroll 1
    for (int jc = 0; jc < 8; ++jc) {
        const int j0 = jc * 8;
        float racc[8], zacc[8], nia[8], nha[8];
        #pragma unroll
        for (int jj = 0; jj < 8; ++jj) {
            int j = j0 + jj;
            racc[jj] = __ldg(b_ih + j)      + __ldg(b_hh + j);
            zacc[jj] = __ldg(b_ih + 64 + j) + __ldg(b_hh + 64 + j);
            nia[jj]  = __ldg(b_ih + 128 + j);
            nha[jj]  = __ldg(b_hh + 128 + j);
        }
        #pragma unroll 1
        for (int k = 0; k < 64; k += 4) {
            float4 xv = *(const float4*)(shx + t * 68 + k);
            float4 hv = *(const float4*)(shh + t * 68 + k);
            #pragma unroll
            for (int jj = 0; jj < 8; ++jj) {
                int j = j0 + jj;
                float4 wr = *(const float4*)(swt + j * 64 + k);
                float4 wz = *(const float4*)(swt + (64 + j) * 64 + k);
                float4 wn = *(const float4*)(swt + (128 + j) * 64 + k);
                float4 vr = *(const float4*)(swt + 12288 + j * 64 + k);
                float4 vz = *(const float4*)(swt + 12288 + (64 + j) * 64 + k);
                float4 vn = *(const float4*)(swt + 12288 + (128 + j) * 64 + k);
                DOT4(racc[jj], xv, wr);  DOT4(racc[jj], hv, vr);
                DOT4(zacc[jj], xv, wz);  DOT4(zacc[jj], hv, vz);
                DOT4(nia[jj],  xv, wn);  DOT4(nha[jj],  hv, vn);
            }
        }
        #pragma unroll
        for (int jj = 0; jj < 8; ++jj) {
            int j = j0 + jj;
            float r = sig_(racc[jj]);
            float z = sig_(zacc[jj]);
            float n = tanhf(fmaf(r, nha[jj], nia[jj]));
            float hprev = shh[t * 68 + j];
            sxh[t * 68 + j] = (1.f - z) * n + z * hprev;   // park h_new (own row)
        }
    }
    #pragma unroll
    for (int c = 0; c < 16; ++c)  // own row: h_new -> shh
        *(float4*)(shh + t * 68 + c * 4) = *(const float4*)(sxh + t * 68 + c * 4);

    __syncthreads();
    // write h output (coalesced), stage expert group 0 afterwards inside group loop
    {
        float4* hout = (float4*)(out + (size_t)MTOT * 32);
        const float4* hs = (const float4*)shh;
        #pragma unroll
        for (int i = t; i < TPB * 16; i += TPB) {
            int r = i >> 4, c = i & 15;
            hout[(size_t)(base + r) * 16 + c] = hs[r * 17 + c];
        }
    }

    // ---------------- P3: experts (2 groups of 4), gate-weighted mean ----------------
    float fq[32];
    #pragma unroll
    for (int a = 0; a < 32; ++a) fq[a] = 0.f;

    #pragma unroll 1
    for (int g = 0; g < 2; ++g) {
        __syncthreads();
        {
            const float4* s1 = (const float4*)(e_w1 + g * 16384); float4* d1 = (float4*)swt;
            #pragma unroll
            for (int i = t; i < 4096; i += TPB) d1[i] = s1[i];     // 4 experts of [64][64]
            const float4* s2 = (const float4*)(e_w2 + g * 8192);  float4* d2 = (float4*)(swt + 16384);
            #pragma unroll
            for (int i = t; i < 2048; i += TPB) d2[i] = s2[i];     // 4 experts of [32][64]
        }
        __syncthreads();

        #pragma unroll 1
        for (int nl = 0; nl < 4; ++nl) {
            const int n = g * 4 + nl;
            float acc1[64];
            #pragma unroll
            for (int ko = 0; ko < 64; ++ko) acc1[ko] = __ldg(e_b1 + n * 64 + ko);
            #pragma unroll 1
            for (int h = 0; h < 64; h += 4) {
                float4 hv = *(const float4*)(shh + t * 68 + h);
                #pragma unroll
                for (int ko = 0; ko < 64; ++ko) {
                    float4 wv = *(const float4*)(swt + (nl * 64 + ko) * 64 + h);
                    DOT4(acc1[ko], hv, wv);
                }
            }
            #pragma unroll
            for (int c = 0; c < 16; ++c) {   // relu -> park h1 in own sxh row
                float4 v;
                v.x = fmaxf(acc1[c * 4 + 0], 0.f); v.y = fmaxf(acc1[c * 4 + 1], 0.f);
                v.z = fmaxf(acc1[c * 4 + 2], 0.f); v.w = fmaxf(acc1[c * 4 + 3], 0.f);
                *(float4*)(sxh + t * 68 + c * 4) = v;
            }
            float eo[32];
            #pragma unroll
            for (int a = 0; a < 32; ++a) eo[a] = __ldg(e_b2 + n * 32 + a);
            #pragma unroll 1
            for (int k = 0; k < 64; k += 4) {
                float4 av = *(const float4*)(sxh + t * 68 + k);
                #pragma unroll
                for (int a = 0; a < 32; ++a) {
                    float4 wv = *(const float4*)(swt + 16384 + (nl * 32 + a) * 64 + k);
                    DOT4(eo[a], av, wv);
                }
            }
            float wgt = sgate[t * 9 + n];
            #pragma unroll
            for (int a = 0; a < 32; ++a) fq[a] = fmaf(eo[a], wgt, fq[a]);

            __syncthreads();   // previous seo consumers done
            #pragma unroll
            for (int c = 0; c < 8; ++c)
                *(float4*)(seo + t * 36 + c * 4) =
                    make_float4(eo[c*4], eo[c*4+1], eo[c*4+2], eo[c*4+3]);
            __syncthreads();
            {   // experts_out[m][n][a] (coalesced via staging)
                float4* dst = (float4*)(out + (size_t)MTOT * 96);
                const float4* ss = (const float4*)seo;
                #pragma unroll
                for (int i = t; i < TPB * 8; i += TPB) {
                    int r = i >> 3, a4 = i & 7;
                    dst[(size_t)(base + r) * 64 + n * 8 + a4] = ss[r * 9 + a4];
                }
            }
        }
    }

    // ---------------- final_q = mean over experts ----------------
    __syncthreads();
    #pragma unroll
    for (int c = 0; c < 8; ++c)
        *(float4*)(seo + t * 36 + c * 4) =
            make_float4(fq[c*4] * 0.125f, fq[c*4+1] * 0.125f,
                        fq[c*4+2] * 0.125f, fq[c*4+3] * 0.125f);
    __syncthreads();
    {
        float4* dst = (float4*)out;
        const float4* ss = (const float4*)seo;
        #pragma unroll
        for (int i = t; i < TPB * 8; i += TPB) {
            int r = i >> 3, a4 = i & 7;
            dst[(size_t)(base + r) * 8 + a4] = ss[r * 9 + a4];
        }
    }
}

extern "C" void kernel_launch(void* const* d_in, const int* in_sizes, int n_in,
                              void* d_out, int out_size) {
    (void)in_sizes; (void)n_in; (void)out_size;
    cudaFuncSetAttribute(msp_kernel, cudaFuncAttributeMaxDynamicSharedMemorySize,
                         SMEM_FLOATS * 4);
    msp_kernel<<<NBLK, TPB, SMEM_FLOATS * 4>>>(
        (const float*)d_in[0],  // inputs        [M,128]
        (const float*)d_in[1],  // hidden_state  [M,64]
        (const float*)d_in[2],  // fc_w          [64,128]
        (const float*)d_in[3],  // fc_b          [64]
        (const float*)d_in[4],  // w_ih          [192,64]
        (const float*)d_in[5],  // w_hh          [192,64]
        (const float*)d_in[6],  // b_ih          [192]
        (const float*)d_in[7],  // b_hh          [192]
        (const float*)d_in[8],  // e_w1          [8,64,64]
        (const float*)d_in[9],  // e_b1          [8,64]
        (const float*)d_in[10], // e_w2          [8,32,64]
        (const float*)d_in[11], // e_b2          [8,32]
        (const float*)d_in[12], // gate_w        [8,128]
        (const float*)d_in[13], // gate_b        [8]
        (float*)d_out);
}

// round 2
// speedup vs baseline: 2.7858x; 2.7858x over previous
#include <cuda_runtime.h>
#include <math.h>
#include <stdint.h>

#define MTOT 131072
#define TPB  256
#define TOK  128
#define NBLK (MTOT / TOK)

// shared-memory strides (floats)
#define XHS  132   // [128][132]  x|h tile (stride%32==4 -> conflict-free scalar A loads)
#define BUFS 68    // [128][68]   staging (x_in halves, h raw, h1)
#define WS   72    // packed weight rows, K=64 (stride%32==8 -> conflict-free LDS.64)
#define FCS  136   // packed weight rows, K=128

// shared-memory offsets (floats)
#define SW_OFF    0
#define WHH_OFF   13824
#define EW2_OFF   18432
#define SXH_OFF   27648
#define SBUF_OFF  44544
#define SGATE_OFF 53248
#define SMEMF     54400   // 217,600 bytes

__device__ __forceinline__ float f2tf_f(float f) {
    uint32_t u;
    asm("cvt.rna.tf32.f32 %0, %1;" : "=r"(u) : "f"(f));
    return __uint_as_float(u);
}
__device__ __forceinline__ float sig_(float v) { return 1.0f / (1.0f + __expf(-v)); }

// D += A(16x8) * B(8x8), tf32 inputs, f32 accum
__device__ __forceinline__ void mma8(float* d,
    uint32_t a0, uint32_t a1, uint32_t a2, uint32_t a3,
    uint32_t b0, uint32_t b1)
{
    asm volatile(
        "mma.sync.aligned.m16n8k8.row.col.f32.tf32.tf32.f32 "
        "{%0,%1,%2,%3}, {%4,%5,%6,%7}, {%8,%9}, {%0,%1,%2,%3};"
        : "+f"(d[0]), "+f"(d[1]), "+f"(d[2]), "+f"(d[3])
        : "r"(a0), "r"(a1), "r"(a2), "r"(a3), "r"(b0), "r"(b1));
}

// pack k index so pair (k0+t, k0+t+4) is 8B-contiguous: pos = 8*(k/8) + 2*(k%4) + ((k%8)>=4)
__device__ __forceinline__ int packpos(int k) {
    return ((k >> 3) << 3) + ((k & 3) << 1) + ((k >> 2) & 1);
}

#define LOAD_A(ptr, stride)                                        \
    uint32_t a0 = __float_as_uint((ptr)[tig]);                     \
    uint32_t a2 = __float_as_uint((ptr)[tig + 4]);                 \
    uint32_t a1 = __float_as_uint((ptr)[8 * (stride) + tig]);      \
    uint32_t a3 = __float_as_uint((ptr)[8 * (stride) + tig + 4]);

__global__ void __launch_bounds__(TPB) msp_mma(
    const float* __restrict__ xin,   const float* __restrict__ hin,
    const float* __restrict__ fc_w,  const float* __restrict__ fc_b,
    const float* __restrict__ w_ih,  const float* __restrict__ w_hh,
    const float* __restrict__ b_ih,  const float* __restrict__ b_hh,
    const float* __restrict__ e_w1,  const float* __restrict__ e_b1,
    const float* __restrict__ e_w2,  const float* __restrict__ e_b2,
    const float* __restrict__ gate_w,const float* __restrict__ gate_b,
    float* __restrict__ out)
{
    extern __shared__ float sm[];
    float* s_w    = sm + SW_OFF;
    float* s_xh   = sm + SXH_OFF;
    float* s_buf  = sm + SBUF_OFF;
    float* s_gate = sm + SGATE_OFF;

    const int t    = threadIdx.x;
    const int lane = t & 31;
    const int wid  = t >> 5;
    const int gid  = lane >> 2;
    const int tig  = lane & 3;
    const int r0   = wid << 4;          // warp-owned M stripe [r0, r0+16)
    const int base = blockIdx.x * TOK;
    const int row0 = r0 + gid, row1 = row0 + 8;

    // ---------------- prologue staging ----------------
    {
        const float4* hsrc = (const float4*)hin;
        #pragma unroll
        for (int i = t; i < TOK * 16; i += TPB) {        // h_in (raw) -> s_xh cols 64..127
            int r = i >> 4, c = i & 15;
            *(float4*)(s_xh + r * XHS + 64 + c * 4) = hsrc[(size_t)(base + r) * 16 + c];
        }
        const float4* xsrc = (const float4*)xin;
        #pragma unroll
        for (int i = t; i < TOK * 16; i += TPB) {        // x_in cols 0..63 (tf32) -> s_buf
            int r = i >> 4, c = i & 15;
            float4 v = xsrc[(size_t)(base + r) * 32 + c];
            v.x = f2tf_f(v.x); v.y = f2tf_f(v.y); v.z = f2tf_f(v.z); v.w = f2tf_f(v.w);
            *(float4*)(s_buf + r * BUFS + c * 4) = v;
        }
        for (int i = t; i < 64 * 128; i += TPB) {        // fc_w packed
            int j = i >> 7, k = i & 127;
            s_w[j * FCS + packpos(k)] = f2tf_f(__ldg(fc_w + i));
        }
        for (int i = t; i < 8 * 128; i += TPB) {         // gate_w packed
            int j = i >> 7, k = i & 127;
            s_w[(64 + j) * FCS + packpos(k)] = f2tf_f(__ldg(gate_w + i));
        }
    }
    __syncthreads();

    // ---------------- Stage A: x = relu(x_in @ fc_w^T), gate pre-act ----------------
    {
        float accF[8][4], accG[4];
        #pragma unroll
        for (int nt = 0; nt < 8; ++nt) {
            float b0 = __ldg(fc_b + nt * 8 + 2 * tig);
            float b1 = __ldg(fc_b + nt * 8 + 2 * tig + 1);
            accF[nt][0] = b0; accF[nt][1] = b1; accF[nt][2] = b0; accF[nt][3] = b1;
        }
        {
            float g0 = __ldg(gate_b + 2 * tig), g1 = __ldg(gate_b + 2 * tig + 1);
            accG[0] = g0; accG[1] = g1; accG[2] = g0; accG[3] = g1;
        }

        #pragma unroll
        for (int half = 0; half < 2; ++half) {
            if (half == 1) {
                __syncthreads();
                const float4* xsrc = (const float4*)xin;
                #pragma unroll
                for (int i = t; i < TOK * 16; i += TPB) {   // x_in cols 64..127
                    int r = i >> 4, c = i & 15;
                    float4 v = xsrc[(size_t)(base + r) * 32 + 16 + c];
                    v.x = f2tf_f(v.x); v.y = f2tf_f(v.y); v.z = f2tf_f(v.z); v.w = f2tf_f(v.w);
                    *(float4*)(s_buf + r * BUFS + c * 4) = v;
                }
                __syncthreads();
            }
            #pragma unroll
            for (int k0 = 0; k0 < 8; ++k0) {
                const float* ar = s_buf + row0 * BUFS + k0 * 8;
                LOAD_A(ar, BUFS)
                const int kb = (half * 8 + k0) * 8 + 2 * tig;
                #pragma unroll
                for (int nt = 0; nt < 8; ++nt) {
                    uint2 bv = *(const uint2*)(s_w + (nt * 8 + gid) * FCS + kb);
                    mma8(accF[nt], a0, a1, a2, a3, bv.x, bv.y);
                }
                uint2 gv = *(const uint2*)(s_w + (64 + gid) * FCS + kb);
                mma8(accG, a0, a1, a2, a3, gv.x, gv.y);
            }
        }
        // epilogue: relu(x) -> s_xh cols 0..63 (tf32); sigmoid(gate) -> s_gate
        #pragma unroll
        for (int nt = 0; nt < 8; ++nt) {
            int c0 = nt * 8 + 2 * tig;
            s_xh[row0 * XHS + c0]     = f2tf_f(fmaxf(accF[nt][0], 0.f));
            s_xh[row0 * XHS + c0 + 1] = f2tf_f(fmaxf(accF[nt][1], 0.f));
            s_xh[row1 * XHS + c0]     = f2tf_f(fmaxf(accF[nt][2], 0.f));
            s_xh[row1 * XHS + c0 + 1] = f2tf_f(fmaxf(accF[nt][3], 0.f));
        }
        s_gate[row0 * 9 + 2 * tig]     = sig_(accG[0]);
        s_gate[row0 * 9 + 2 * tig + 1] = sig_(accG[1]);
        s_gate[row1 * 9 + 2 * tig]     = sig_(accG[2]);
        s_gate[row1 * 9 + 2 * tig + 1] = sig_(accG[3]);
    }
    __syncthreads();

    // ---------------- pack GRU weights ----------------
    for (int i = t; i < 192 * 64; i += TPB) {
        int j = i >> 6, k = i & 63;
        int p = j * WS + packpos(k);
        s_w[p]           = f2tf_f(__ldg(w_ih + i));
        s_w[WHH_OFF + p] = f2tf_f(__ldg(w_hh + i));
    }
    __syncthreads();

    // ---------------- Stage B: GRU cell ----------------
    {
        float aRZ[16][4], aGN[8][4], aHN[8][4];
        #pragma unroll
        for (int nt = 0; nt < 16; ++nt) {
            int j0 = nt * 8 + 2 * tig;
            float b0 = __ldg(b_ih + j0)     + __ldg(b_hh + j0);
            float b1 = __ldg(b_ih + j0 + 1) + __ldg(b_hh + j0 + 1);
            aRZ[nt][0] = b0; aRZ[nt][1] = b1; aRZ[nt][2] = b0; aRZ[nt][3] = b1;
        }
        #pragma unroll
        for (int nt = 0; nt < 8; ++nt) {
            int j0 = 128 + nt * 8 + 2 * tig;
            float g0 = __ldg(b_ih + j0), g1 = __ldg(b_ih + j0 + 1);
            aGN[nt][0] = g0; aGN[nt][1] = g1; aGN[nt][2] = g0; aGN[nt][3] = g1;
            float h0 = __ldg(b_hh + j0), h1v = __ldg(b_hh + j0 + 1);
            aHN[nt][0] = h0; aHN[nt][1] = h1v; aHN[nt][2] = h0; aHN[nt][3] = h1v;
        }
        // k 0..63: A = x, B = w_ih  (rz rows 0..127, n rows 128..191)
        #pragma unroll
        for (int ks = 0; ks < 8; ++ks) {
            const float* ar = s_xh + row0 * XHS + ks * 8;
            LOAD_A(ar, XHS)
            const int kb = ks * 8 + 2 * tig;
            #pragma unroll
            for (int nt = 0; nt < 16; ++nt) {
                uint2 bv = *(const uint2*)(s_w + (nt * 8 + gid) * WS + kb);
                mma8(aRZ[nt], a0, a1, a2, a3, bv.x, bv.y);
            }
            #pragma unroll
            for (int nt = 0; nt < 8; ++nt) {
                uint2 bv = *(const uint2*)(s_w + (128 + nt * 8 + gid) * WS + kb);
                mma8(aGN[nt], a0, a1, a2, a3, bv.x, bv.y);
            }
        }
        // k 64..127: A = h_in, B = w_hh
        #pragma unroll
        for (int ks = 0; ks < 8; ++ks) {
            const float* ar = s_xh + row0 * XHS + 64 + ks * 8;
            LOAD_A(ar, XHS)
            const int kb = ks * 8 + 2 * tig;
            #pragma unroll
            for (int nt = 0; nt < 16; ++nt) {
                uint2 bv = *(const uint2*)(s_w + WHH_OFF + (nt * 8 + gid) * WS + kb);
                mma8(aRZ[nt], a0, a1, a2, a3, bv.x, bv.y);
            }
            #pragma unroll
            for (int nt = 0; nt < 8; ++nt) {
                uint2 bv = *(const uint2*)(s_w + WHH_OFF + (128 + nt * 8 + gid) * WS + kb);
                mma8(aHN[nt], a0, a1, a2, a3, bv.x, bv.y);
            }
        }
        // epilogue: h = (1-z)n + z*h_prev ; raw h -> s_buf, tf32 h -> s_xh cols 0..63
        #pragma unroll
        for (int nt = 0; nt < 8; ++nt) {
            #pragma unroll
            for (int e = 0; e < 4; ++e) {
                int row = (e & 2) ? row1 : row0;
                int j = nt * 8 + 2 * tig + (e & 1);
                float r_ = sig_(aRZ[nt][e]);
                float z_ = sig_(aRZ[nt + 8][e]);
                float n_ = tanhf(fmaf(r_, aHN[nt][e], aGN[nt][e]));
                float hp = s_xh[row * XHS + 64 + j];
                float h_ = fmaf(z_, hp - n_, n_);
                s_buf[row * BUFS + j] = h_;
                s_xh[row * XHS + j]  = f2tf_f(h_);
            }
        }
    }
    __syncthreads();

    // h output (coalesced)
    {
        float4* hout = (float4*)(out + (size_t)MTOT * 32);
        #pragma unroll
        for (int i = t; i < TOK * 16; i += TPB) {
            int r = i >> 4, c = i & 15;
            hout[(size_t)(base + r) * 16 + c] = *(const float4*)(s_buf + r * BUFS + c * 4);
        }
    }

    // ---------------- Stage C/D: experts ----------------
    float fq[4][4];
    #pragma unroll
    for (int nt = 0; nt < 4; ++nt) { fq[nt][0] = fq[nt][1] = fq[nt][2] = fq[nt][3] = 0.f; }

    float* eobase = out + (size_t)MTOT * 96;

    #pragma unroll
    for (int gb = 0; gb < 2; ++gb) {
        if (gb == 1) __syncthreads();   // wait group-0 consumers
        for (int i = t; i < 4 * 64 * 64; i += TPB) {     // e_w1 group
            int j = i >> 6, k = i & 63;
            s_w[j * WS + packpos(k)] = f2tf_f(__ldg(e_w1 + gb * 16384 + i));
        }
        for (int i = t; i < 4 * 32 * 64; i += TPB) {     // e_w2 group
            int j = i >> 6, k = i & 63;
            s_w[EW2_OFF + j * WS + packpos(k)] = f2tf_f(__ldg(e_w2 + gb * 8192 + i));
        }
        __syncthreads();

        #pragma unroll
        for (int nl = 0; nl < 4; ++nl) {
            const int n = gb * 4 + nl;
            float acc1[8][4];
            #pragma unroll
            for (int nt = 0; nt < 8; ++nt) {
                float b0 = __ldg(e_b1 + n * 64 + nt * 8 + 2 * tig);
                float b1 = __ldg(e_b1 + n * 64 + nt * 8 + 2 * tig + 1);
                acc1[nt][0] = b0; acc1[nt][1] = b1; acc1[nt][2] = b0; acc1[nt][3] = b1;
            }
            #pragma unroll
            for (int k = 0; k < 8; ++k) {
                const float* ar = s_xh + row0 * XHS + k * 8;   // h (tf32)
                LOAD_A(ar, XHS)
                const int kb = k * 8 + 2 * tig;
                #pragma unroll
                for (int nt = 0; nt < 8; ++nt) {
                    uint2 bv = *(const uint2*)(s_w + (nl * 64 + nt * 8 + gid) * WS + kb);
                    mma8(acc1[nt], a0, a1, a2, a3, bv.x, bv.y);
                }
            }
            __syncwarp();              // prior nl's s_buf reads (cross-lane) done
            #pragma unroll
            for (int nt = 0; nt < 8; ++nt) {               // relu(h1) -> s_buf (tf32)
                int c0 = nt * 8 + 2 * tig;
                s_buf[row0 * BUFS + c0]     = f2tf_f(fmaxf(acc1[nt][0], 0.f));
                s_buf[row0 * BUFS + c0 + 1] = f2tf_f(fmaxf(acc1[nt][1], 0.f));
                s_buf[row1 * BUFS + c0]     = f2tf_f(fmaxf(acc1[nt][2], 0.f));
                s_buf[row1 * BUFS + c0 + 1] = f2tf_f(fmaxf(acc1[nt][3], 0.f));
            }
            __syncwarp();

            float acc2[4][4];
            #pragma unroll
            for (int nt = 0; nt < 4; ++nt) {
                float b0 = __ldg(e_b2 + n * 32 + nt * 8 + 2 * tig);
                float b1 = __ldg(e_b2 + n * 32 + nt * 8 + 2 * tig + 1);
                acc2[nt][0] = b0; acc2[nt][1] = b1; acc2[nt][2] = b0; acc2[nt][3] = b1;
            }
            #pragma unroll
            for (int k = 0; k < 8; ++k) {
                const float* ar = s_buf + row0 * BUFS + k * 8;
                LOAD_A(ar, BUFS)
                const int kb = k * 8 + 2 * tig;
                #pragma unroll
                for (int nt = 0; nt < 4; ++nt) {
                    uint2 bv = *(const uint2*)(s_w + EW2_OFF + (nl * 32 + nt * 8 + gid) * WS + kb);
                    mma8(acc2[nt], a0, a1, a2, a3, bv.x, bv.y);
                }
            }
            // epilogue: experts_out store + gated accumulation
            float w0 = s_gate[row0 * 9 + n];
            float w1 = s_gate[row1 * 9 + n];
            #pragma unroll
            for (int nt = 0; nt < 4; ++nt) {
                fq[nt][0] = fmaf(acc2[nt][0], w0, fq[nt][0]);
                fq[nt][1] = fmaf(acc2[nt][1], w0, fq[nt][1]);
                fq[nt][2] = fmaf(acc2[nt][2], w1, fq[nt][2]);
                fq[nt][3] = fmaf(acc2[nt][3], w1, fq[nt][3]);
                int c0 = n * 32 + nt * 8 + 2 * tig;
                *(float2*)(eobase + (size_t)(base + row0) * 256 + c0) =
                    make_float2(acc2[nt][0], acc2[nt][1]);
                *(float2*)(eobase + (size_t)(base + row1) * 256 + c0) =
                    make_float2(acc2[nt][2], acc2[nt][3]);
            }
        }
    }

    // ---------------- final_q = (1/8) * sum_n gate_n * eo_n ----------------
    #pragma unroll
    for (int nt = 0; nt < 4; ++nt) {
        int c0 = nt * 8 + 2 * tig;
        *(float2*)(out + (size_t)(base + row0) * 32 + c0) =
            make_float2(fq[nt][0] * 0.125f, fq[nt][1] * 0.125f);
        *(float2*)(out + (size_t)(base + row1) * 32 + c0) =
            make_float2(fq[nt][2] * 0.125f, fq[nt][3] * 0.125f);
    }
}

extern "C" void kernel_launch(void* const* d_in, const int* in_sizes, int n_in,
                              void* d_out, int out_size) {
    (void)in_sizes; (void)n_in; (void)out_size;
    cudaFuncSetAttribute(msp_mma, cudaFuncAttributeMaxDynamicSharedMemorySize,
                         SMEMF * 4);
    msp_mma<<<NBLK, TPB, SMEMF * 4>>>(
        (const float*)d_in[0],  (const float*)d_in[1],
        (const float*)d_in[2],  (const float*)d_in[3],
        (const float*)d_in[4],  (const float*)d_in[5],
        (const float*)d_in[6],  (const float*)d_in[7],
        (const float*)d_in[8],  (const float*)d_in[9],
        (const float*)d_in[10], (const float*)d_in[11],
        (const float*)d_in[12], (const float*)d_in[13],
        (float*)d_out);
}

// round 3
// speedup vs baseline: 2.9463x; 1.0576x over previous
#include <cuda_runtime.h>
#include <math.h>
#include <stdint.h>

#define MTOT 131072
#define TPB  256
#define TOK  128
#define NBLK (MTOT / TOK)

#define XHS 132   // x|h tile row stride (floats): cols 0..63 x_in/x/h1, 64..127 h_in/h
#define WS  72    // packed K=64 weight row stride
#define FCS 136   // packed K=128 weight row stride

// smem float offsets
#define SW_OFF    0
#define SXH_OFF   9792
#define SGATE_OFF 26688   // 9792 + 128*132
#define SMEMF     27840   // 111,360 bytes -> 2 CTAs/SM

// packed-weight global offsets (floats)
#define GW_FC   0         // [64][136] fc + [8][136] gate = 9792 (one contiguous stage-A block)
#define GW_GRU  9792      // 4 j-chunks x (ih[48][72] + hh[48][72]) = 27648
#define GW_E1   37440     // [8][64][72]
#define GW_E2   74304     // [8][32][72]
#define GW_TOT  92736

__device__ __align__(16) float g_wp[GW_TOT];

__device__ __forceinline__ float f2tf_f(float f) {
    uint32_t u; asm("cvt.rna.tf32.f32 %0, %1;" : "=r"(u) : "f"(f));
    return __uint_as_float(u);
}
__device__ __forceinline__ float sig_(float v) { return 1.0f / (1.0f + __expf(-v)); }
// pair (k, k+4) made 8B-contiguous for single LDS.64 B-fragment loads
__device__ __forceinline__ int packpos(int k) {
    return ((k >> 3) << 3) + ((k & 3) << 1) + ((k >> 2) & 1);
}

__device__ __forceinline__ void mma8(float* d,
    uint32_t a0, uint32_t a1, uint32_t a2, uint32_t a3, uint32_t b0, uint32_t b1)
{
    asm volatile(
        "mma.sync.aligned.m16n8k8.row.col.f32.tf32.tf32.f32 "
        "{%0,%1,%2,%3}, {%4,%5,%6,%7}, {%8,%9}, {%0,%1,%2,%3};"
        : "+f"(d[0]), "+f"(d[1]), "+f"(d[2]), "+f"(d[3])
        : "r"(a0), "r"(a1), "r"(a2), "r"(a3), "r"(b0), "r"(b1));
}

#define LOAD_A(ptr, stride)                                        \
    uint32_t a0 = __float_as_uint((ptr)[tig]);                     \
    uint32_t a2 = __float_as_uint((ptr)[tig + 4]);                 \
    uint32_t a1 = __float_as_uint((ptr)[8 * (stride) + tig]);      \
    uint32_t a3 = __float_as_uint((ptr)[8 * (stride) + tig + 4]);

// ---------------- prep: pack + tf32-convert all weights once per launch ----------------
__global__ void prep_pack(const float* __restrict__ fc_w, const float* __restrict__ gate_w,
                          const float* __restrict__ w_ih, const float* __restrict__ w_hh,
                          const float* __restrict__ e_w1, const float* __restrict__ e_w2)
{
    int tid = blockIdx.x * blockDim.x + threadIdx.x;
    int nth = gridDim.x * blockDim.x;
    for (int i = tid; i < 64 * 128; i += nth) {
        int j = i >> 7, k = i & 127;
        g_wp[GW_FC + j * FCS + packpos(k)] = f2tf_f(__ldg(fc_w + i));
    }
    for (int i = tid; i < 8 * 128; i += nth) {
        int j = i >> 7, k = i & 127;
        g_wp[GW_FC + (64 + j) * FCS + packpos(k)] = f2tf_f(__ldg(gate_w + i));
    }
    for (int i = tid; i < 192 * 64; i += nth) {
        int R = i >> 6, k = i & 63;
        int c = (R & 63) >> 4, grp = R >> 6, lr = grp * 16 + (R & 15);
        int d = GW_GRU + c * 6912 + lr * WS + packpos(k);
        g_wp[d]        = f2tf_f(__ldg(w_ih + i));
        g_wp[d + 3456] = f2tf_f(__ldg(w_hh + i));
    }
    for (int i = tid; i < 8 * 64 * 64; i += nth) {
        int n = i >> 12, r = (i >> 6) & 63, k = i & 63;
        g_wp[GW_E1 + n * 4608 + r * WS + packpos(k)] = f2tf_f(__ldg(e_w1 + i));
    }
    for (int i = tid; i < 8 * 32 * 64; i += nth) {
        int n = i >> 11, r = (i >> 6) & 31, k = i & 63;
        g_wp[GW_E2 + n * 2304 + r * WS + packpos(k)] = f2tf_f(__ldg(e_w2 + i));
    }
}

// ---------------- main ----------------
__global__ void __launch_bounds__(TPB, 2) msp_main(
    const float* __restrict__ xin,  const float* __restrict__ hin,
    const float* __restrict__ fc_b,
    const float* __restrict__ b_ih, const float* __restrict__ b_hh,
    const float* __restrict__ e_b1, const float* __restrict__ e_b2,
    const float* __restrict__ gate_b,
    float* __restrict__ out)
{
    extern __shared__ float sm[];
    float* s_w    = sm + SW_OFF;
    float* s_xh   = sm + SXH_OFF;
    float* s_gate = sm + SGATE_OFF;

    const int t = threadIdx.x, lane = t & 31, wid = t >> 5;
    const int gid = lane >> 2, tig = lane & 3;
    const int r0 = wid << 4, base = blockIdx.x * TOK;
    const int row0 = r0 + gid, row1 = row0 + 8;

    // ---- prologue: h_in raw -> cols 64..127, x_in half0 (RNA) -> cols 0..63, stage-A weights ----
    {
        const float4* hsrc = (const float4*)hin;
        for (int i = t; i < TOK * 16; i += TPB) {
            int r = i >> 4, c = i & 15;
            *(float4*)(s_xh + r * XHS + 64 + c * 4) = hsrc[(size_t)(base + r) * 16 + c];
        }
        const float4* xsrc = (const float4*)xin;
        for (int i = t; i < TOK * 16; i += TPB) {
            int r = i >> 4, c = i & 15;
            float4 v = xsrc[(size_t)(base + r) * 32 + c];
            v.x = f2tf_f(v.x); v.y = f2tf_f(v.y); v.z = f2tf_f(v.z); v.w = f2tf_f(v.w);
            *(float4*)(s_xh + r * XHS + c * 4) = v;
        }
        const float4* s = (const float4*)(g_wp + GW_FC);
        float4* d = (float4*)s_w;
        for (int i = t; i < 9792 / 4; i += TPB) d[i] = s[i];
    }
    __syncthreads();

    // ---- Stage A: x = relu(x_in @ fc_w^T + b), gate = sigmoid(x_in @ gate_w^T + b) ----
    {
        float accF[8][4], accG[4];
        #pragma unroll
        for (int nt = 0; nt < 8; ++nt) {
            float b0 = __ldg(fc_b + nt * 8 + 2 * tig), b1 = __ldg(fc_b + nt * 8 + 2 * tig + 1);
            accF[nt][0] = b0; accF[nt][1] = b1; accF[nt][2] = b0; accF[nt][3] = b1;
        }
        {
            float g0 = __ldg(gate_b + 2 * tig), g1 = __ldg(gate_b + 2 * tig + 1);
            accG[0] = g0; accG[1] = g1; accG[2] = g0; accG[3] = g1;
        }
        #pragma unroll
        for (int half = 0; half < 2; ++half) {
            if (half == 1) {
                __syncthreads();
                const float4* xsrc = (const float4*)xin;
                for (int i = t; i < TOK * 16; i += TPB) {
                    int r = i >> 4, c = i & 15;
                    float4 v = xsrc[(size_t)(base + r) * 32 + 16 + c];
                    v.x = f2tf_f(v.x); v.y = f2tf_f(v.y); v.z = f2tf_f(v.z); v.w = f2tf_f(v.w);
                    *(float4*)(s_xh + r * XHS + c * 4) = v;
                }
                __syncthreads();
            }
            #pragma unroll
            for (int ks = 0; ks < 8; ++ks) {
                const float* ap = s_xh + row0 * XHS + ks * 8;
                LOAD_A(ap, XHS)
                const int kb = half * 64 + ks * 8 + 2 * tig;
                #pragma unroll
                for (int nt = 0; nt < 8; ++nt) {
                    uint2 bv = *(const uint2*)(s_w + (nt * 8 + gid) * FCS + kb);
                    mma8(accF[nt], a0, a1, a2, a3, bv.x, bv.y);
                }
                uint2 gv = *(const uint2*)(s_w + (64 + gid) * FCS + kb);
                mma8(accG, a0, a1, a2, a3, gv.x, gv.y);
            }
        }
        // epilogue (warp-local rows): x (RNA tf32) -> cols 0..63; gate -> s_gate
        #pragma unroll
        for (int nt = 0; nt < 8; ++nt) {
            int c0 = nt * 8 + 2 * tig;
            s_xh[row0 * XHS + c0]     = f2tf_f(fmaxf(accF[nt][0], 0.f));
            s_xh[row0 * XHS + c0 + 1] = f2tf_f(fmaxf(accF[nt][1], 0.f));
            s_xh[row1 * XHS + c0]     = f2tf_f(fmaxf(accF[nt][2], 0.f));
            s_xh[row1 * XHS + c0 + 1] = f2tf_f(fmaxf(accF[nt][3], 0.f));
        }
        s_gate[row0 * 9 + 2 * tig]     = sig_(accG[0]);
        s_gate[row0 * 9 + 2 * tig + 1] = sig_(accG[1]);
        s_gate[row1 * 9 + 2 * tig]     = sig_(accG[2]);
        s_gate[row1 * 9 + 2 * tig + 1] = sig_(accG[3]);
    }

    // ---- Stage B: GRU in 4 j-chunks of 16 cols; h_new parked in regs until h_in fully consumed ----
    float hpark[24];
    #pragma unroll
    for (int c = 0; c < 4; ++c) {
        __syncthreads();  // prior s_w consumers done
        {
            const float4* s = (const float4*)(g_wp + GW_GRU + c * 6912);
            float4* d = (float4*)s_w;
            for (int i = t; i < 864; i += TPB) d[i] = s[i];   // w_ih chunk [48][72]
        }
        __syncthreads();

        float ar[2][4], az[2][4], ani[2][4], anh[2][4];
        #pragma unroll
        for (int t2 = 0; t2 < 2; ++t2) {
            int j0 = c * 16 + t2 * 8 + 2 * tig;
            float v0 = __ldg(b_ih + j0) + __ldg(b_hh + j0);
            float v1 = __ldg(b_ih + j0 + 1) + __ldg(b_hh + j0 + 1);
            ar[t2][0] = v0; ar[t2][1] = v1; ar[t2][2] = v0; ar[t2][3] = v1;
            float z0 = __ldg(b_ih + 64 + j0) + __ldg(b_hh + 64 + j0);
            float z1 = __ldg(b_ih + 64 + j0 + 1) + __ldg(b_hh + 64 + j0 + 1);
            az[t2][0] = z0; az[t2][1] = z1; az[t2][2] = z0; az[t2][3] = z1;
            float n0 = __ldg(b_ih + 128 + j0), n1 = __ldg(b_ih + 128 + j0 + 1);
            ani[t2][0] = n0; ani[t2][1] = n1; ani[t2][2] = n0; ani[t2][3] = n1;
            float m0 = __ldg(b_hh + 128 + j0), m1 = __ldg(b_hh + 128 + j0 + 1);
            anh[t2][0] = m0; anh[t2][1] = m1; anh[t2][2] = m0; anh[t2][3] = m1;
        }
        // x-part: A = x (cols 0..63), B = w_ih chunk (local rows: r 0..15, z 16..31, n 32..47)
        #pragma unroll
        for (int ks = 0; ks < 8; ++ks) {
            const float* ap = s_xh + row0 * XHS + ks * 8;
            LOAD_A(ap, XHS)
            const int kb = ks * 8 + 2 * tig;
            #pragma unroll
            for (int t2 = 0; t2 < 2; ++t2) {
                uint2 br = *(const uint2*)(s_w + (t2 * 8 + gid) * WS + kb);
                mma8(ar[t2], a0, a1, a2, a3, br.x, br.y);
                uint2 bz = *(const uint2*)(s_w + (16 + t2 * 8 + gid) * WS + kb);
                mma8(az[t2], a0, a1, a2, a3, bz.x, bz.y);
                uint2 bn = *(const uint2*)(s_w + (32 + t2 * 8 + gid) * WS + kb);
                mma8(ani[t2], a0, a1, a2, a3, bn.x, bn.y);
            }
        }
        __syncthreads();
        {
            const float4* s = (const float4*)(g_wp + GW_GRU + c * 6912 + 3456);
            float4* d = (float4*)s_w;
            for (int i = t; i < 864; i += TPB) d[i] = s[i];   // w_hh chunk
        }
        __syncthreads();
        // h-part: A = h_in (cols 64..127)
        #pragma unroll
        for (int ks = 0; ks < 8; ++ks) {
            const float* ap = s_xh + row0 * XHS + 64 + ks * 8;
            LOAD_A(ap, XHS)
            const int kb = ks * 8 + 2 * tig;
            #pragma unroll
            for (int t2 = 0; t2 < 2; ++t2) {
                uint2 br = *(const uint2*)(s_w + (t2 * 8 + gid) * WS + kb);
                mma8(ar[t2], a0, a1, a2, a3, br.x, br.y);
                uint2 bz = *(const uint2*)(s_w + (16 + t2 * 8 + gid) * WS + kb);
                mma8(az[t2], a0, a1, a2, a3, bz.x, bz.y);
                uint2 bn = *(const uint2*)(s_w + (32 + t2 * 8 + gid) * WS + kb);
                mma8(anh[t2], a0, a1, a2, a3, bn.x, bn.y);
            }
        }
        // epilogue: chunks 0..2 park h_new (h_in still needed as A by later chunks); chunk 3 writes
        #pragma unroll
        for (int t2 = 0; t2 < 2; ++t2) {
            #pragma unroll
            for (int e = 0; e < 4; ++e) {
                int row = (e & 2) ? row1 : row0;
                int j = c * 16 + t2 * 8 + 2 * tig + (e & 1);
                float rr = sig_(ar[t2][e]);
                float zz = sig_(az[t2][e]);
                float nn = tanhf(fmaf(rr, anh[t2][e], ani[t2][e]));
                float hp = s_xh[row * XHS + 64 + j];
                float hh = fmaf(zz, hp - nn, nn);
                if (c < 3) hpark[c * 8 + t2 * 4 + e] = hh;
                else       s_xh[row * XHS + 64 + j] = hh;
            }
        }
    }
    // flush parked h_new (warp-local rows)
    #pragma unroll
    for (int c = 0; c < 3; ++c) {
        #pragma unroll
        for (int t2 = 0; t2 < 2; ++t2) {
            #pragma unroll
            for (int e = 0; e < 4; ++e) {
                int row = (e & 2) ? row1 : row0;
                int j = c * 16 + t2 * 8 + 2 * tig + (e & 1);
                s_xh[row * XHS + 64 + j] = hpark[c * 8 + t2 * 4 + e];
            }
        }
    }
    __syncthreads();

    // ---- h output (coalesced) ----
    {
        float4* hout = (float4*)(out + (size_t)MTOT * 32);
        for (int i = t; i < TOK * 16; i += TPB) {
            int r = i >> 4, c = i & 15;
            hout[(size_t)(base + r) * 16 + c] = *(const float4*)(s_xh + r * XHS + 64 + c * 4);
        }
    }

    // ---- Stage C/D: 8 experts, one at a time ----
    float fq[4][4];
    #pragma unroll
    for (int q = 0; q < 4; ++q) { fq[q][0] = fq[q][1] = fq[q][2] = fq[q][3] = 0.f; }
    float* eobase = out + (size_t)MTOT * 96;

    #pragma unroll 1
    for (int n = 0; n < 8; ++n) {
        __syncthreads();  // prior s_w consumers done (incl. h-out copy reads on first iter)
        {
            const float4* s1 = (const float4*)(g_wp + GW_E1 + n * 4608);
            float4* d1 = (float4*)s_w;
            for (int i = t; i < 1152; i += TPB) d1[i] = s1[i];
            const float4* s2 = (const float4*)(g_wp + GW_E2 + n * 2304);
            float4* d2 = (float4*)(s_w + 64 * WS);
            for (int i = t; i < 576; i += TPB) d2[i] = s2[i];
        }
        __syncthreads();

        float acc1[8][4];
        #pragma unroll
        for (int nt = 0; nt < 8; ++nt) {
            float b0 = __ldg(e_b1 + n * 64 + nt * 8 + 2 * tig);
            float b1 = __ldg(e_b1 + n * 64 + nt * 8 + 2 * tig + 1);
            acc1[nt][0] = b0; acc1[nt][1] = b1; acc1[nt][2] = b0; acc1[nt][3] = b1;
        }
        #pragma unroll
        for (int ks = 0; ks < 8; ++ks) {
            const float* ap = s_xh + row0 * XHS + 64 + ks * 8;   // h (raw)
            LOAD_A(ap, XHS)
            const int kb = ks * 8 + 2 * tig;
            #pragma unroll
            for (int nt = 0; nt < 8; ++nt) {
                uint2 bv = *(const uint2*)(s_w + (nt * 8 + gid) * WS + kb);
                mma8(acc1[nt], a0, a1, a2, a3, bv.x, bv.y);
            }
        }
        __syncwarp();
        #pragma unroll
        for (int nt = 0; nt < 8; ++nt) {   // relu(h1) RNA -> cols 0..63 (warp-local rows)
            int c0 = nt * 8 + 2 * tig;
            s_xh[row0 * XHS + c0]     = f2tf_f(fmaxf(acc1[nt][0], 0.f));
            s_xh[row0 * XHS + c0 + 1] = f2tf_f(fmaxf(acc1[nt][1], 0.f));
            s_xh[row1 * XHS + c0]     = f2tf_f(fmaxf(acc1[nt][2], 0.f));
            s_xh[row1 * XHS + c0 + 1] = f2tf_f(fmaxf(acc1[nt][3], 0.f));
        }
        __syncwarp();

        float acc2[4][4];
        #pragma unroll
        for (int nt = 0; nt < 4; ++nt) {
            float b0 = __ldg(e_b2 + n * 32 + nt * 8 + 2 * tig);
            float b1 = __ldg(e_b2 + n * 32 + nt * 8 + 2 * tig + 1);
            acc2[nt][0] = b0; acc2[nt][1] = b1; acc2[nt][2] = b0; acc2[nt][3] = b1;
        }
        #pragma unroll
        for (int ks = 0; ks < 8; ++ks) {
            const float* ap = s_xh + row0 * XHS + ks * 8;        // h1 (tf32)
            LOAD_A(ap, XHS)
            const int kb = ks * 8 + 2 * tig;
            #pragma unroll
            for (int nt = 0; nt < 4; ++nt) {
                uint2 bv = *(const uint2*)(s_w + (64 + nt * 8 + gid) * WS + kb);
                mma8(acc2[nt], a0, a1, a2, a3, bv.x, bv.y);
            }
        }
        float w0 = s_gate[row0 * 9 + n], w1 = s_gate[row1 * 9 + n];
        #pragma unroll
        for (int nt = 0; nt < 4; ++nt) {
            fq[nt][0] = fmaf(acc2[nt][0], w0, fq[nt][0]);
            fq[nt][1] = fmaf(acc2[nt][1], w0, fq[nt][1]);
            fq[nt][2] = fmaf(acc2[nt][2], w1, fq[nt][2]);
            fq[nt][3] = fmaf(acc2[nt][3], w1, fq[nt][3]);
            int c0 = n * 32 + nt * 8 + 2 * tig;
            *(float2*)(eobase + (size_t)(base + row0) * 256 + c0) =
                make_float2(acc2[nt][0], acc2[nt][1]);
            *(float2*)(eobase + (size_t)(base + row1) * 256 + c0) =
                make_float2(acc2[nt][2], acc2[nt][3]);
        }
    }

    // ---- final_q ----
    #pragma unroll
    for (int nt = 0; nt < 4; ++nt) {
        int c0 = nt * 8 + 2 * tig;
        *(float2*)(out + (size_t)(base + row0) * 32 + c0) =
            make_float2(fq[nt][0] * 0.125f, fq[nt][1] * 0.125f);
        *(float2*)(out + (size_t)(base + row1) * 32 + c0) =
            make_float2(fq[nt][2] * 0.125f, fq[nt][3] * 0.125f);
    }
}

extern "C" void kernel_launch(void* const* d_in, const int* in_sizes, int n_in,
                              void* d_out, int out_size) {
    (void)in_sizes; (void)n_in; (void)out_size;
    prep_pack<<<128, 256>>>(
        (const float*)d_in[2],  (const float*)d_in[12],
        (const float*)d_in[4],  (const float*)d_in[5],
        (const float*)d_in[8],  (const float*)d_in[10]);
    cudaFuncSetAttribute(msp_main, cudaFuncAttributeMaxDynamicSharedMemorySize, SMEMF * 4);
    msp_main<<<NBLK, TPB, SMEMF * 4>>>(
        (const float*)d_in[0],  (const float*)d_in[1],
        (const float*)d_in[3],
        (const float*)d_in[6],  (const float*)d_in[7],
        (const float*)d_in[9],  (const float*)d_in[11],
        (const float*)d_in[13],
        (float*)d_out);
}